// round 5
// baseline (speedup 1.0000x reference)
#include <cuda_runtime.h>
#include <math.h>

#define TOT     128000
#define HDIM    64
#define NHEADS  4
#define DHEAD   16
#define FIN     32
#define NEDGE   512000
#define NB      128
#define OBSD    1500
#define HSD     512
#define NOUTD   15
#define VHD     128
#define NA      15
#define NLAYER  4

// ---------------- scratch (device globals; no allocation allowed) ----------------
__device__ __align__(16) float g_x[TOT * HDIM];
__device__ __align__(16) float g_qkv[TOT * 192];     // packed q|k|v per node
__device__ __align__(16) float g_buf[TOT * HDIM];    // attention aggregate
__device__ __align__(16) float g_hid[TOT * 2 * HDIM];// FFN hidden
__device__ __align__(16) float g_wqkv[NLAYER * HDIM * 192]; // packed QKV weights
__device__ int g_counts[TOT];
__device__ int g_fill[TOT];
__device__ int g_rowptr[TOT + 1];
__device__ int g_csrc[NEDGE];
__device__ __align__(16) float g_gat[NB * NA];
__device__ __align__(16) float g_feat[NB * HSD];
__device__ __align__(16) float g_feat2[NB * HSD];
__device__ __align__(16) float g_vh[NB * VHD];
__device__ __align__(16) float g_vh2[NB * VHD];

// ---------------- CSR build ----------------
__global__ void zero_counts_kernel() {
    int i = blockIdx.x * blockDim.x + threadIdx.x;
    if (i < TOT) { g_counts[i] = 0; g_fill[i] = 0; }
}

__global__ void count_edges_kernel(const int* __restrict__ edge_dst) {
    int e = blockIdx.x * blockDim.x + threadIdx.x;
    if (e < NEDGE) atomicAdd(&g_counts[edge_dst[e]], 1);
}

__global__ void scan_kernel() {
    __shared__ int wsum[32];
    __shared__ int carry;
    int tid = threadIdx.x;
    int lane = tid & 31, wid = tid >> 5;
    if (tid == 0) carry = 0;
    __syncthreads();
    for (int base = 0; base < TOT; base += 1024) {
        int i = base + tid;
        int val = (i < TOT) ? g_counts[i] : 0;
        int s = val;
        #pragma unroll
        for (int off = 1; off < 32; off <<= 1) {
            int t = __shfl_up_sync(0xffffffffu, s, off);
            if (lane >= off) s += t;
        }
        if (lane == 31) wsum[wid] = s;
        __syncthreads();
        if (wid == 0) {
            int ws = wsum[lane];
            #pragma unroll
            for (int off = 1; off < 32; off <<= 1) {
                int t = __shfl_up_sync(0xffffffffu, ws, off);
                if (lane >= off) ws += t;
            }
            wsum[lane] = ws;
        }
        __syncthreads();
        int pre = (wid > 0) ? wsum[wid - 1] : 0;
        int incl = pre + s;
        if (i < TOT) g_rowptr[i] = carry + incl - val;
        __syncthreads();
        if (tid == 0) carry += wsum[31];
        __syncthreads();
    }
    if (tid == 0) g_rowptr[TOT] = carry;
}

__global__ void scatter_edges_kernel(const int* __restrict__ edge_src,
                                     const int* __restrict__ edge_dst) {
    int e = blockIdx.x * blockDim.x + threadIdx.x;
    if (e < NEDGE) {
        int d = edge_dst[e];
        int pos = atomicAdd(&g_fill[d], 1);
        g_csrc[g_rowptr[d] + pos] = edge_src[e];
    }
}

// ---------------- pack QKV weights: [L,64,64]x3 -> [L,64,192] ----------------
__global__ void pack_qkv_kernel(const float* __restrict__ Wq,
                                const float* __restrict__ Wk,
                                const float* __restrict__ Wv) {
    int idx = blockIdx.x * blockDim.x + threadIdx.x;
    if (idx >= NLAYER * HDIM * HDIM) return;
    int l = idx >> 12;            // /4096
    int rem = idx & 4095;
    int k = rem >> 6, c = rem & 63;
    float* dst = &g_wqkv[(l * HDIM + k) * 192];
    dst[c]       = Wq[idx];
    dst[64 + c]  = Wk[idx];
    dst[128 + c] = Wv[idx];
}

// ---------------- tf32 tensor-core GEMM ----------------
__device__ __forceinline__ unsigned tf32u(float x) {
    float r;
    asm("cvt.rna.tf32.f32 %0, %1;" : "=f"(r) : "f"(x));
    return __float_as_uint(r);
}

// C[M,N] = A[M,K] @ B[K,N] (+bias)(+relu). BM=128, BN=64, BK=32, 256 thr.
__global__ __launch_bounds__(256) void gemm_tf32_kernel(
    const float* __restrict__ A, const float* __restrict__ B,
    const float* __restrict__ bias, float* __restrict__ C,
    int N, int K, int act)
{
    __shared__ float As[128][36];
    __shared__ float Bs[32][72];
    int bm = blockIdx.y * 128, bn = blockIdx.x * 64;
    int tid = threadIdx.x;
    int warp = tid >> 5, lane = tid & 31;
    int g = lane >> 2, t = lane & 3;

    float acc[8][4];
    #pragma unroll
    for (int j = 0; j < 8; j++)
        #pragma unroll
        for (int i = 0; i < 4; i++) acc[j][i] = 0.0f;

    for (int k0 = 0; k0 < K; k0 += 32) {
        #pragma unroll
        for (int i = 0; i < 4; i++) {
            int idx = i * 256 + tid;
            int r = idx >> 3;
            int c = (idx & 7) * 4;
            float4 v = *(const float4*)&A[(size_t)(bm + r) * K + k0 + c];
            As[r][c + 0] = __uint_as_float(tf32u(v.x));
            As[r][c + 1] = __uint_as_float(tf32u(v.y));
            As[r][c + 2] = __uint_as_float(tf32u(v.z));
            As[r][c + 3] = __uint_as_float(tf32u(v.w));
        }
        #pragma unroll
        for (int i = 0; i < 2; i++) {
            int idx = i * 256 + tid;
            int r = idx >> 4;
            int c = (idx & 15) * 4;
            float4 v = *(const float4*)&B[(size_t)(k0 + r) * N + bn + c];
            Bs[r][c + 0] = __uint_as_float(tf32u(v.x));
            Bs[r][c + 1] = __uint_as_float(tf32u(v.y));
            Bs[r][c + 2] = __uint_as_float(tf32u(v.z));
            Bs[r][c + 3] = __uint_as_float(tf32u(v.w));
        }
        __syncthreads();
        #pragma unroll
        for (int ks = 0; ks < 4; ks++) {
            int kk = ks * 8;
            unsigned a0 = __float_as_uint(As[warp * 16 + g][kk + t]);
            unsigned a1 = __float_as_uint(As[warp * 16 + g + 8][kk + t]);
            unsigned a2 = __float_as_uint(As[warp * 16 + g][kk + t + 4]);
            unsigned a3 = __float_as_uint(As[warp * 16 + g + 8][kk + t + 4]);
            #pragma unroll
            for (int j = 0; j < 8; j++) {
                unsigned b0 = __float_as_uint(Bs[kk + t][j * 8 + g]);
                unsigned b1 = __float_as_uint(Bs[kk + t + 4][j * 8 + g]);
                asm volatile(
                    "mma.sync.aligned.m16n8k8.row.col.f32.tf32.tf32.f32 "
                    "{%0,%1,%2,%3}, {%4,%5,%6,%7}, {%8,%9}, {%0,%1,%2,%3};"
                    : "+f"(acc[j][0]), "+f"(acc[j][1]), "+f"(acc[j][2]), "+f"(acc[j][3])
                    : "r"(a0), "r"(a1), "r"(a2), "r"(a3), "r"(b0), "r"(b1));
            }
        }
        __syncthreads();
    }
    int row0 = bm + warp * 16 + g;
    #pragma unroll
    for (int j = 0; j < 8; j++) {
        int col = bn + j * 8 + t * 2;
        float v0 = acc[j][0], v1 = acc[j][1], v2 = acc[j][2], v3 = acc[j][3];
        if (bias) {
            float bb0 = bias[col], bb1 = bias[col + 1];
            v0 += bb0; v1 += bb1; v2 += bb0; v3 += bb1;
        }
        if (act) {
            v0 = fmaxf(v0, 0.0f); v1 = fmaxf(v1, 0.0f);
            v2 = fmaxf(v2, 0.0f); v3 = fmaxf(v3, 0.0f);
        }
        float2 w0; w0.x = v0; w0.y = v1;
        float2 w1; w1.x = v2; w1.y = v3;
        *(float2*)&C[(size_t)row0 * N + col] = w0;
        *(float2*)&C[(size_t)(row0 + 8) * N + col] = w1;
    }
}

// GEMM (N=64 fixed) with fused bias + residual-add + LayerNorm epilogue.
// X[M,64] = LN( A@B (+bias) + X ) * gamma + beta     (X = g_x, in-place)
// Each row of 64 is held by 4 lanes (same g); reduce via shfl_xor 1,2.
__global__ __launch_bounds__(256) void gemm_tf32_ln_kernel(
    const float* __restrict__ A, const float* __restrict__ B,
    const float* __restrict__ bias, float* __restrict__ X,
    const float* __restrict__ gamma, const float* __restrict__ beta,
    int K)
{
    const int N = 64;
    __shared__ float As[128][36];
    __shared__ float Bs[32][72];
    int bm = blockIdx.y * 128;
    int tid = threadIdx.x;
    int warp = tid >> 5, lane = tid & 31;
    int g = lane >> 2, t = lane & 3;

    float acc[8][4];
    #pragma unroll
    for (int j = 0; j < 8; j++)
        #pragma unroll
        for (int i = 0; i < 4; i++) acc[j][i] = 0.0f;

    for (int k0 = 0; k0 < K; k0 += 32) {
        #pragma unroll
        for (int i = 0; i < 4; i++) {
            int idx = i * 256 + tid;
            int r = idx >> 3;
            int c = (idx & 7) * 4;
            float4 v = *(const float4*)&A[(size_t)(bm + r) * K + k0 + c];
            As[r][c + 0] = __uint_as_float(tf32u(v.x));
            As[r][c + 1] = __uint_as_float(tf32u(v.y));
            As[r][c + 2] = __uint_as_float(tf32u(v.z));
            As[r][c + 3] = __uint_as_float(tf32u(v.w));
        }
        #pragma unroll
        for (int i = 0; i < 2; i++) {
            int idx = i * 256 + tid;
            int r = idx >> 4;
            int c = (idx & 15) * 4;
            float4 v = *(const float4*)&B[(size_t)(k0 + r) * N + c];
            Bs[r][c + 0] = __uint_as_float(tf32u(v.x));
            Bs[r][c + 1] = __uint_as_float(tf32u(v.y));
            Bs[r][c + 2] = __uint_as_float(tf32u(v.z));
            Bs[r][c + 3] = __uint_as_float(tf32u(v.w));
        }
        __syncthreads();
        #pragma unroll
        for (int ks = 0; ks < 4; ks++) {
            int kk = ks * 8;
            unsigned a0 = __float_as_uint(As[warp * 16 + g][kk + t]);
            unsigned a1 = __float_as_uint(As[warp * 16 + g + 8][kk + t]);
            unsigned a2 = __float_as_uint(As[warp * 16 + g][kk + t + 4]);
            unsigned a3 = __float_as_uint(As[warp * 16 + g + 8][kk + t + 4]);
            #pragma unroll
            for (int j = 0; j < 8; j++) {
                unsigned b0 = __float_as_uint(Bs[kk + t][j * 8 + g]);
                unsigned b1 = __float_as_uint(Bs[kk + t + 4][j * 8 + g]);
                asm volatile(
                    "mma.sync.aligned.m16n8k8.row.col.f32.tf32.tf32.f32 "
                    "{%0,%1,%2,%3}, {%4,%5,%6,%7}, {%8,%9}, {%0,%1,%2,%3};"
                    : "+f"(acc[j][0]), "+f"(acc[j][1]), "+f"(acc[j][2]), "+f"(acc[j][3])
                    : "r"(a0), "r"(a1), "r"(a2), "r"(a3), "r"(b0), "r"(b1));
            }
        }
        __syncthreads();
    }

    // ---- fused epilogue: bias + residual + LayerNorm ----
    int row0 = bm + warp * 16 + g;
    int row1 = row0 + 8;
    float sum0 = 0.0f, sum1 = 0.0f;
    #pragma unroll
    for (int j = 0; j < 8; j++) {
        int col = j * 8 + t * 2;
        float bb0 = 0.0f, bb1 = 0.0f;
        if (bias) { bb0 = bias[col]; bb1 = bias[col + 1]; }
        float2 r0 = *(const float2*)&X[(size_t)row0 * N + col];
        float2 r1 = *(const float2*)&X[(size_t)row1 * N + col];
        acc[j][0] += bb0 + r0.x; acc[j][1] += bb1 + r0.y;
        acc[j][2] += bb0 + r1.x; acc[j][3] += bb1 + r1.y;
        sum0 += acc[j][0] + acc[j][1];
        sum1 += acc[j][2] + acc[j][3];
    }
    sum0 += __shfl_xor_sync(0xffffffffu, sum0, 1);
    sum0 += __shfl_xor_sync(0xffffffffu, sum0, 2);
    sum1 += __shfl_xor_sync(0xffffffffu, sum1, 1);
    sum1 += __shfl_xor_sync(0xffffffffu, sum1, 2);
    float m0 = sum0 * (1.0f / 64.0f);
    float m1 = sum1 * (1.0f / 64.0f);
    float var0 = 0.0f, var1 = 0.0f;
    #pragma unroll
    for (int j = 0; j < 8; j++) {
        float d0 = acc[j][0] - m0, d1 = acc[j][1] - m0;
        float d2 = acc[j][2] - m1, d3 = acc[j][3] - m1;
        var0 += d0 * d0 + d1 * d1;
        var1 += d2 * d2 + d3 * d3;
    }
    var0 += __shfl_xor_sync(0xffffffffu, var0, 1);
    var0 += __shfl_xor_sync(0xffffffffu, var0, 2);
    var1 += __shfl_xor_sync(0xffffffffu, var1, 1);
    var1 += __shfl_xor_sync(0xffffffffu, var1, 2);
    float rs0 = rsqrtf(var0 * (1.0f / 64.0f) + 1e-5f);
    float rs1 = rsqrtf(var1 * (1.0f / 64.0f) + 1e-5f);
    #pragma unroll
    for (int j = 0; j < 8; j++) {
        int col = j * 8 + t * 2;
        float2 gg = *(const float2*)&gamma[col];
        float2 bb = *(const float2*)&beta[col];
        float2 w0, w1;
        w0.x = (acc[j][0] - m0) * rs0 * gg.x + bb.x;
        w0.y = (acc[j][1] - m0) * rs0 * gg.y + bb.y;
        w1.x = (acc[j][2] - m1) * rs1 * gg.x + bb.x;
        w1.y = (acc[j][3] - m1) * rs1 * gg.y + bb.y;
        *(float2*)&X[(size_t)row0 * N + col] = w0;
        *(float2*)&X[(size_t)row1 * N + col] = w1;
    }
}

// ---------------- GAT attention: warp per dst node, single-pass online softmax ----------------
__global__ __launch_bounds__(256) void gat_attn_kernel() {
    int warp = (blockIdx.x * blockDim.x + threadIdx.x) >> 5;
    int lane = threadIdx.x & 31;
    if (warp >= TOT) return;
    int node = warp;
    int beg = g_rowptr[node], end = g_rowptr[node + 1];
    const float2* qkv2 = (const float2*)g_qkv;      // stride 96 float2 per node
    float2 qv = qkv2[(size_t)node * 96 + lane];
    const float scale = 0.25f;  // 1/sqrt(16)
    float m = -INFINITY, denom = 0.0f, a0 = 0.0f, a1 = 0.0f;
    for (int e = beg; e < end; e++) {
        int s = g_csrc[e];
        float2 kv = qkv2[(size_t)s * 96 + 32 + lane];
        float d = qv.x * kv.x + qv.y * kv.y;
        d += __shfl_xor_sync(0xffffffffu, d, 1);
        d += __shfl_xor_sync(0xffffffffu, d, 2);
        d += __shfl_xor_sync(0xffffffffu, d, 4);
        d *= scale;
        float mn = fmaxf(m, d);
        float f = __expf(m - mn);       // first iter: exp(-inf)=0
        float w = __expf(d - mn);
        float2 vv = qkv2[(size_t)s * 96 + 64 + lane];
        denom = denom * f + w;
        a0 = a0 * f + w * vv.x;
        a1 = a1 * f + w * vv.y;
        m = mn;
    }
    float invd = 1.0f / (denom + 1e-9f);
    float2 o; o.x = a0 * invd; o.y = a1 * invd;
    ((float2*)g_buf)[(size_t)node * 32 + lane] = o;
}

// ---------------- readout ----------------
__global__ void readout_kernel(const int* __restrict__ agent_nodes,
                               const float* __restrict__ Wr, const float* __restrict__ br)
{
    int i = blockIdx.x * blockDim.x + threadIdx.x;
    if (i >= NB * NA) return;
    int bi = i / NA, a = i % NA;
    int node = agent_nodes[bi];
    float s = br[a];
    #pragma unroll
    for (int h = 0; h < HDIM; h++) s += g_x[node * HDIM + h] * Wr[h * NA + a];
    g_gat[i] = s;
}

// ---------------- FC heads (fp32), 4-way ILP ----------------
__global__ __launch_bounds__(256) void fc_kernel(
    const float* __restrict__ A, const float* __restrict__ W,
    const float* __restrict__ bias, float* __restrict__ C,
    int in_dim, int out_dim, int act)
{
    __shared__ float srow[1536];
    int row = blockIdx.x;
    for (int i = threadIdx.x; i < in_dim; i += blockDim.x)
        srow[i] = A[row * in_dim + i];
    __syncthreads();
    int k4 = in_dim & ~3;
    for (int j = threadIdx.x; j < out_dim; j += blockDim.x) {
        float s0 = 0.f, s1 = 0.f, s2 = 0.f, s3 = 0.f;
        int k = 0;
        for (; k < k4; k += 4) {
            s0 += srow[k + 0] * W[(k + 0) * out_dim + j];
            s1 += srow[k + 1] * W[(k + 1) * out_dim + j];
            s2 += srow[k + 2] * W[(k + 2) * out_dim + j];
            s3 += srow[k + 3] * W[(k + 3) * out_dim + j];
        }
        for (; k < in_dim; k++) s0 += srow[k] * W[k * out_dim + j];
        float s = (bias ? bias[j] : 0.0f) + (s0 + s1) + (s2 + s3);
        if (act == 1) s = tanhf(s);
        C[row * out_dim + j] = s;
    }
}

__global__ __launch_bounds__(256) void fc_concat_kernel(
    const float* __restrict__ obs, const float* __restrict__ W,
    const float* __restrict__ bias)
{
    __shared__ float srow[1536];
    int row = blockIdx.x;
    for (int i = threadIdx.x; i < NA; i += blockDim.x) srow[i] = g_gat[row * NA + i];
    for (int i = threadIdx.x; i < OBSD; i += blockDim.x) srow[NA + i] = obs[row * OBSD + i];
    __syncthreads();
    const int in_dim = NA + OBSD;
    int k4 = in_dim & ~3;
    for (int j = threadIdx.x; j < HSD; j += blockDim.x) {
        float s0 = 0.f, s1 = 0.f, s2 = 0.f, s3 = 0.f;
        int k = 0;
        for (; k < k4; k += 4) {
            s0 += srow[k + 0] * W[(k + 0) * HSD + j];
            s1 += srow[k + 1] * W[(k + 1) * HSD + j];
            s2 += srow[k + 2] * W[(k + 2) * HSD + j];
            s3 += srow[k + 3] * W[(k + 3) * HSD + j];
        }
        for (; k < in_dim; k++) s0 += srow[k] * W[k * HSD + j];
        float s = bias[j] + (s0 + s1) + (s2 + s3);
        g_feat[row * HSD + j] = tanhf(s);
    }
}

__global__ void value_kernel(const float* __restrict__ Wvo, const float* __restrict__ bvo,
                             float* __restrict__ out)
{
    int bi = threadIdx.x;
    if (bi >= NB) return;
    float s = bvo[0];
    #pragma unroll
    for (int k = 0; k < VHD; k++) s += g_vh2[bi * VHD + k] * Wvo[k];
    out[NB * NOUTD + bi] = s;
}

// ---------------- launch ----------------
extern "C" void kernel_launch(void* const* d_in, const int* in_sizes, int n_in,
                              void* d_out, int out_size)
{
    const float* node_feats = (const float*)d_in[0];
    const float* obs        = (const float*)d_in[1];
    const int*   edge_src   = (const int*)d_in[2];
    const int*   edge_dst   = (const int*)d_in[3];
    const int*   agent_nodes= (const int*)d_in[4];
    const float* W_in = (const float*)d_in[5];
    const float* Wq   = (const float*)d_in[6];
    const float* Wk   = (const float*)d_in[7];
    const float* Wv   = (const float*)d_in[8];
    const float* Wo   = (const float*)d_in[9];
    const float* ln1g = (const float*)d_in[10];
    const float* ln1b = (const float*)d_in[11];
    const float* W1   = (const float*)d_in[12];
    const float* b1   = (const float*)d_in[13];
    const float* W2   = (const float*)d_in[14];
    const float* b2   = (const float*)d_in[15];
    const float* ln2g = (const float*)d_in[16];
    const float* ln2b = (const float*)d_in[17];
    const float* Wr   = (const float*)d_in[18];
    const float* br   = (const float*)d_in[19];
    const float* Wp1  = (const float*)d_in[20];
    const float* bp1  = (const float*)d_in[21];
    const float* Wp2  = (const float*)d_in[22];
    const float* bp2  = (const float*)d_in[23];
    const float* Wlog = (const float*)d_in[24];
    const float* blog = (const float*)d_in[25];
    const float* Wv1  = (const float*)d_in[26];
    const float* bv1  = (const float*)d_in[27];
    const float* Wv2  = (const float*)d_in[28];
    const float* bv2  = (const float*)d_in[29];
    const float* Wvo  = (const float*)d_in[30];
    const float* bvo  = (const float*)d_in[31];
    float* out = (float*)d_out;

    float *x, *qkv, *buf, *hid, *wqkv, *feat, *feat2, *vh, *vh2;
    cudaGetSymbolAddress((void**)&x,    g_x);
    cudaGetSymbolAddress((void**)&qkv,  g_qkv);
    cudaGetSymbolAddress((void**)&buf,  g_buf);
    cudaGetSymbolAddress((void**)&hid,  g_hid);
    cudaGetSymbolAddress((void**)&wqkv, g_wqkv);
    cudaGetSymbolAddress((void**)&feat, g_feat);
    cudaGetSymbolAddress((void**)&feat2,g_feat2);
    cudaGetSymbolAddress((void**)&vh,   g_vh);
    cudaGetSymbolAddress((void**)&vh2,  g_vh2);

    const int MB = TOT / 128;  // 1000 row blocks

    // CSR build + weight packing
    zero_counts_kernel<<<(TOT + 255) / 256, 256>>>();
    count_edges_kernel<<<(NEDGE + 255) / 256, 256>>>(edge_dst);
    scan_kernel<<<1, 1024>>>();
    scatter_edges_kernel<<<(NEDGE + 255) / 256, 256>>>(edge_src, edge_dst);
    pack_qkv_kernel<<<(NLAYER * HDIM * HDIM + 255) / 256, 256>>>(Wq, Wk, Wv);

    // input projection: x = node_feats @ W_in   [TOT,32]@[32,64]
    gemm_tf32_kernel<<<dim3(1, MB), 256>>>(node_feats, W_in, nullptr, x, 64, 32, 0);

    for (int l = 0; l < NLAYER; l++) {
        // fused QKV projection: qkv = x @ Wqkv_l   [TOT,64]@[64,192]
        gemm_tf32_kernel<<<dim3(3, MB), 256>>>(x, wqkv + l * HDIM * 192, nullptr,
                                               qkv, 192, 64, 0);
        gat_attn_kernel<<<TOT / 8, 256>>>();
        // x = LN(x + buf @ Wo_l)
        gemm_tf32_ln_kernel<<<dim3(1, MB), 256>>>(buf, Wo + l * HDIM * HDIM, nullptr,
                                                  x, ln1g + l * HDIM, ln1b + l * HDIM, 64);
        // hid = relu(x @ W1_l + b1_l)
        gemm_tf32_kernel<<<dim3(2, MB), 256>>>(x, W1 + l * HDIM * 2 * HDIM, b1 + l * 2 * HDIM,
                                               hid, 2 * HDIM, HDIM, 1);
        // x = LN(x + hid @ W2_l + b2_l)
        gemm_tf32_ln_kernel<<<dim3(1, MB), 256>>>(hid, W2 + l * 2 * HDIM * HDIM, b2 + l * HDIM,
                                                  x, ln2g + l * HDIM, ln2b + l * HDIM, 128);
    }

    // heads (fp32, small)
    readout_kernel<<<(NB * NA + 255) / 256, 256>>>(agent_nodes, Wr, br);
    fc_concat_kernel<<<NB, 256>>>(obs, Wp1, bp1);
    fc_kernel<<<NB, 256>>>(feat, Wp2, bp2, feat2, HSD, HSD, 1);
    fc_kernel<<<NB, 256>>>(feat2, Wlog, blog, out, HSD, NOUTD, 0);
    fc_kernel<<<NB, 256>>>(obs, Wv1, bv1, vh, OBSD, VHD, 1);
    fc_kernel<<<NB, 256>>>(vh, Wv2, bv2, vh2, VHD, VHD, 1);
    value_kernel<<<1, 128>>>(Wvo, bvo, out);
}

// round 6
// speedup vs baseline: 1.0204x; 1.0204x over previous
#include <cuda_runtime.h>
#include <math.h>

#define TOT     128000
#define HDIM    64
#define NHEADS  4
#define DHEAD   16
#define FIN     32
#define NEDGE   512000
#define NB      128
#define OBSD    1500
#define HSD     512
#define NOUTD   15
#define VHD     128
#define NA      15
#define NLAYER  4

// ---------------- scratch (device globals; no allocation allowed) ----------------
__device__ __align__(16) float g_x[TOT * HDIM];
__device__ __align__(16) float g_q[TOT * HDIM];      // streamed q
__device__ __align__(16) float g_kv[TOT * 128];      // packed k|v per node (gather set)
__device__ __align__(16) float g_buf[TOT * HDIM];    // attention aggregate
__device__ __align__(16) float g_hid[TOT * 2 * HDIM];// FFN hidden
__device__ __align__(16) float g_wqkv[NLAYER * HDIM * 192]; // packed QKV weights
__device__ int g_counts[TOT];
__device__ int g_fill[TOT];
__device__ int g_rowptr[TOT + 1];
__device__ int g_csrc[NEDGE];
__device__ __align__(16) float g_gat[NB * NA];
__device__ __align__(16) float g_feat[NB * HSD];
__device__ __align__(16) float g_feat2[NB * HSD];
__device__ __align__(16) float g_vh[NB * VHD];
__device__ __align__(16) float g_vh2[NB * VHD];

// ---------------- CSR build ----------------
__global__ void zero_counts_kernel() {
    int i = blockIdx.x * blockDim.x + threadIdx.x;
    if (i < TOT) { g_counts[i] = 0; g_fill[i] = 0; }
}

__global__ void count_edges_kernel(const int* __restrict__ edge_dst) {
    int e = blockIdx.x * blockDim.x + threadIdx.x;
    if (e < NEDGE) atomicAdd(&g_counts[edge_dst[e]], 1);
}

__global__ void scan_kernel() {
    __shared__ int wsum[32];
    __shared__ int carry;
    int tid = threadIdx.x;
    int lane = tid & 31, wid = tid >> 5;
    if (tid == 0) carry = 0;
    __syncthreads();
    for (int base = 0; base < TOT; base += 1024) {
        int i = base + tid;
        int val = (i < TOT) ? g_counts[i] : 0;
        int s = val;
        #pragma unroll
        for (int off = 1; off < 32; off <<= 1) {
            int t = __shfl_up_sync(0xffffffffu, s, off);
            if (lane >= off) s += t;
        }
        if (lane == 31) wsum[wid] = s;
        __syncthreads();
        if (wid == 0) {
            int ws = wsum[lane];
            #pragma unroll
            for (int off = 1; off < 32; off <<= 1) {
                int t = __shfl_up_sync(0xffffffffu, ws, off);
                if (lane >= off) ws += t;
            }
            wsum[lane] = ws;
        }
        __syncthreads();
        int pre = (wid > 0) ? wsum[wid - 1] : 0;
        int incl = pre + s;
        if (i < TOT) g_rowptr[i] = carry + incl - val;
        __syncthreads();
        if (tid == 0) carry += wsum[31];
        __syncthreads();
    }
    if (tid == 0) g_rowptr[TOT] = carry;
}

__global__ void scatter_edges_kernel(const int* __restrict__ edge_src,
                                     const int* __restrict__ edge_dst) {
    int e = blockIdx.x * blockDim.x + threadIdx.x;
    if (e < NEDGE) {
        int d = edge_dst[e];
        int pos = atomicAdd(&g_fill[d], 1);
        g_csrc[g_rowptr[d] + pos] = edge_src[e];
    }
}

// ---------------- pack QKV weights: [L,64,64]x3 -> [L,64,192] ----------------
__global__ void pack_qkv_kernel(const float* __restrict__ Wq,
                                const float* __restrict__ Wk,
                                const float* __restrict__ Wv) {
    int idx = blockIdx.x * blockDim.x + threadIdx.x;
    if (idx >= NLAYER * HDIM * HDIM) return;
    int l = idx >> 12;
    int rem = idx & 4095;
    int k = rem >> 6, c = rem & 63;
    float* dst = &g_wqkv[(l * HDIM + k) * 192];
    dst[c]       = Wq[idx];
    dst[64 + c]  = Wk[idx];
    dst[128 + c] = Wv[idx];
}

// ---------------- tf32 tensor-core GEMM ----------------
__device__ __forceinline__ unsigned tf32u(float x) {
    float r;
    asm("cvt.rna.tf32.f32 %0, %1;" : "=f"(r) : "f"(x));
    return __float_as_uint(r);
}

// C[M,N] = A[M,K] @ B[K,N] (+bias)(+relu). BM=128, BN=64, BK=32, 256 thr.
__global__ __launch_bounds__(256) void gemm_tf32_kernel(
    const float* __restrict__ A, const float* __restrict__ B,
    const float* __restrict__ bias, float* __restrict__ C,
    int N, int K, int act)
{
    __shared__ float As[128][36];
    __shared__ float Bs[32][72];
    int bm = blockIdx.y * 128, bn = blockIdx.x * 64;
    int tid = threadIdx.x;
    int warp = tid >> 5, lane = tid & 31;
    int g = lane >> 2, t = lane & 3;

    float acc[8][4];
    #pragma unroll
    for (int j = 0; j < 8; j++)
        #pragma unroll
        for (int i = 0; i < 4; i++) acc[j][i] = 0.0f;

    for (int k0 = 0; k0 < K; k0 += 32) {
        #pragma unroll
        for (int i = 0; i < 4; i++) {
            int idx = i * 256 + tid;
            int r = idx >> 3;
            int c = (idx & 7) * 4;
            float4 v = *(const float4*)&A[(size_t)(bm + r) * K + k0 + c];
            As[r][c + 0] = __uint_as_float(tf32u(v.x));
            As[r][c + 1] = __uint_as_float(tf32u(v.y));
            As[r][c + 2] = __uint_as_float(tf32u(v.z));
            As[r][c + 3] = __uint_as_float(tf32u(v.w));
        }
        #pragma unroll
        for (int i = 0; i < 2; i++) {
            int idx = i * 256 + tid;
            int r = idx >> 4;
            int c = (idx & 15) * 4;
            float4 v = *(const float4*)&B[(size_t)(k0 + r) * N + bn + c];
            Bs[r][c + 0] = __uint_as_float(tf32u(v.x));
            Bs[r][c + 1] = __uint_as_float(tf32u(v.y));
            Bs[r][c + 2] = __uint_as_float(tf32u(v.z));
            Bs[r][c + 3] = __uint_as_float(tf32u(v.w));
        }
        __syncthreads();
        #pragma unroll
        for (int ks = 0; ks < 4; ks++) {
            int kk = ks * 8;
            unsigned a0 = __float_as_uint(As[warp * 16 + g][kk + t]);
            unsigned a1 = __float_as_uint(As[warp * 16 + g + 8][kk + t]);
            unsigned a2 = __float_as_uint(As[warp * 16 + g][kk + t + 4]);
            unsigned a3 = __float_as_uint(As[warp * 16 + g + 8][kk + t + 4]);
            #pragma unroll
            for (int j = 0; j < 8; j++) {
                unsigned b0 = __float_as_uint(Bs[kk + t][j * 8 + g]);
                unsigned b1 = __float_as_uint(Bs[kk + t + 4][j * 8 + g]);
                asm volatile(
                    "mma.sync.aligned.m16n8k8.row.col.f32.tf32.tf32.f32 "
                    "{%0,%1,%2,%3}, {%4,%5,%6,%7}, {%8,%9}, {%0,%1,%2,%3};"
                    : "+f"(acc[j][0]), "+f"(acc[j][1]), "+f"(acc[j][2]), "+f"(acc[j][3])
                    : "r"(a0), "r"(a1), "r"(a2), "r"(a3), "r"(b0), "r"(b1));
            }
        }
        __syncthreads();
    }
    int row0 = bm + warp * 16 + g;
    #pragma unroll
    for (int j = 0; j < 8; j++) {
        int col = bn + j * 8 + t * 2;
        float v0 = acc[j][0], v1 = acc[j][1], v2 = acc[j][2], v3 = acc[j][3];
        if (bias) {
            float bb0 = bias[col], bb1 = bias[col + 1];
            v0 += bb0; v1 += bb1; v2 += bb0; v3 += bb1;
        }
        if (act) {
            v0 = fmaxf(v0, 0.0f); v1 = fmaxf(v1, 0.0f);
            v2 = fmaxf(v2, 0.0f); v3 = fmaxf(v3, 0.0f);
        }
        float2 w0; w0.x = v0; w0.y = v1;
        float2 w1; w1.x = v2; w1.y = v3;
        *(float2*)&C[(size_t)row0 * N + col] = w0;
        *(float2*)&C[(size_t)(row0 + 8) * N + col] = w1;
    }
}

// Fused QKV GEMM: A[M,64] @ Wqkv[64,192]; column-block 0 -> q[M,64] (stream),
// blocks 1,2 -> kv[M,128] packed (k cols 0-63, v cols 64-127).  K=64 fixed.
__global__ __launch_bounds__(256) void gemm_qkv_kernel(
    const float* __restrict__ A, const float* __restrict__ B,
    float* __restrict__ Cq, float* __restrict__ Ckv)
{
    const int N = 192, K = 64;
    __shared__ float As[128][36];
    __shared__ float Bs[32][72];
    int bm = blockIdx.y * 128, bn = blockIdx.x * 64;
    int tid = threadIdx.x;
    int warp = tid >> 5, lane = tid & 31;
    int g = lane >> 2, t = lane & 3;

    float acc[8][4];
    #pragma unroll
    for (int j = 0; j < 8; j++)
        #pragma unroll
        for (int i = 0; i < 4; i++) acc[j][i] = 0.0f;

    for (int k0 = 0; k0 < K; k0 += 32) {
        #pragma unroll
        for (int i = 0; i < 4; i++) {
            int idx = i * 256 + tid;
            int r = idx >> 3;
            int c = (idx & 7) * 4;
            float4 v = *(const float4*)&A[(size_t)(bm + r) * K + k0 + c];
            As[r][c + 0] = __uint_as_float(tf32u(v.x));
            As[r][c + 1] = __uint_as_float(tf32u(v.y));
            As[r][c + 2] = __uint_as_float(tf32u(v.z));
            As[r][c + 3] = __uint_as_float(tf32u(v.w));
        }
        #pragma unroll
        for (int i = 0; i < 2; i++) {
            int idx = i * 256 + tid;
            int r = idx >> 4;
            int c = (idx & 15) * 4;
            float4 v = *(const float4*)&B[(size_t)(k0 + r) * N + bn + c];
            Bs[r][c + 0] = __uint_as_float(tf32u(v.x));
            Bs[r][c + 1] = __uint_as_float(tf32u(v.y));
            Bs[r][c + 2] = __uint_as_float(tf32u(v.z));
            Bs[r][c + 3] = __uint_as_float(tf32u(v.w));
        }
        __syncthreads();
        #pragma unroll
        for (int ks = 0; ks < 4; ks++) {
            int kk = ks * 8;
            unsigned a0 = __float_as_uint(As[warp * 16 + g][kk + t]);
            unsigned a1 = __float_as_uint(As[warp * 16 + g + 8][kk + t]);
            unsigned a2 = __float_as_uint(As[warp * 16 + g][kk + t + 4]);
            unsigned a3 = __float_as_uint(As[warp * 16 + g + 8][kk + t + 4]);
            #pragma unroll
            for (int j = 0; j < 8; j++) {
                unsigned b0 = __float_as_uint(Bs[kk + t][j * 8 + g]);
                unsigned b1 = __float_as_uint(Bs[kk + t + 4][j * 8 + g]);
                asm volatile(
                    "mma.sync.aligned.m16n8k8.row.col.f32.tf32.tf32.f32 "
                    "{%0,%1,%2,%3}, {%4,%5,%6,%7}, {%8,%9}, {%0,%1,%2,%3};"
                    : "+f"(acc[j][0]), "+f"(acc[j][1]), "+f"(acc[j][2]), "+f"(acc[j][3])
                    : "r"(a0), "r"(a1), "r"(a2), "r"(a3), "r"(b0), "r"(b1));
            }
        }
        __syncthreads();
    }
    // route output: bn block 0 -> q (ld 64), 1 -> kv cols 0-63, 2 -> kv cols 64-127
    float* Cout;
    int ldc, coff;
    if (blockIdx.x == 0) { Cout = Cq; ldc = 64; coff = 0; }
    else { Cout = Ckv; ldc = 128; coff = (blockIdx.x - 1) * 64; }
    int row0 = bm + warp * 16 + g;
    #pragma unroll
    for (int j = 0; j < 8; j++) {
        int col = coff + j * 8 + t * 2;
        float2 w0; w0.x = acc[j][0]; w0.y = acc[j][1];
        float2 w1; w1.x = acc[j][2]; w1.y = acc[j][3];
        *(float2*)&Cout[(size_t)row0 * ldc + col] = w0;
        *(float2*)&Cout[(size_t)(row0 + 8) * ldc + col] = w1;
    }
}

// GEMM (N=64 fixed) with fused bias + residual-add + LayerNorm epilogue.
__global__ __launch_bounds__(256) void gemm_tf32_ln_kernel(
    const float* __restrict__ A, const float* __restrict__ B,
    const float* __restrict__ bias, float* __restrict__ X,
    const float* __restrict__ gamma, const float* __restrict__ beta,
    int K)
{
    const int N = 64;
    __shared__ float As[128][36];
    __shared__ float Bs[32][72];
    int bm = blockIdx.y * 128;
    int tid = threadIdx.x;
    int warp = tid >> 5, lane = tid & 31;
    int g = lane >> 2, t = lane & 3;

    float acc[8][4];
    #pragma unroll
    for (int j = 0; j < 8; j++)
        #pragma unroll
        for (int i = 0; i < 4; i++) acc[j][i] = 0.0f;

    for (int k0 = 0; k0 < K; k0 += 32) {
        #pragma unroll
        for (int i = 0; i < 4; i++) {
            int idx = i * 256 + tid;
            int r = idx >> 3;
            int c = (idx & 7) * 4;
            float4 v = *(const float4*)&A[(size_t)(bm + r) * K + k0 + c];
            As[r][c + 0] = __uint_as_float(tf32u(v.x));
            As[r][c + 1] = __uint_as_float(tf32u(v.y));
            As[r][c + 2] = __uint_as_float(tf32u(v.z));
            As[r][c + 3] = __uint_as_float(tf32u(v.w));
        }
        #pragma unroll
        for (int i = 0; i < 2; i++) {
            int idx = i * 256 + tid;
            int r = idx >> 4;
            int c = (idx & 15) * 4;
            float4 v = *(const float4*)&B[(size_t)(k0 + r) * N + c];
            Bs[r][c + 0] = __uint_as_float(tf32u(v.x));
            Bs[r][c + 1] = __uint_as_float(tf32u(v.y));
            Bs[r][c + 2] = __uint_as_float(tf32u(v.z));
            Bs[r][c + 3] = __uint_as_float(tf32u(v.w));
        }
        __syncthreads();
        #pragma unroll
        for (int ks = 0; ks < 4; ks++) {
            int kk = ks * 8;
            unsigned a0 = __float_as_uint(As[warp * 16 + g][kk + t]);
            unsigned a1 = __float_as_uint(As[warp * 16 + g + 8][kk + t]);
            unsigned a2 = __float_as_uint(As[warp * 16 + g][kk + t + 4]);
            unsigned a3 = __float_as_uint(As[warp * 16 + g + 8][kk + t + 4]);
            #pragma unroll
            for (int j = 0; j < 8; j++) {
                unsigned b0 = __float_as_uint(Bs[kk + t][j * 8 + g]);
                unsigned b1 = __float_as_uint(Bs[kk + t + 4][j * 8 + g]);
                asm volatile(
                    "mma.sync.aligned.m16n8k8.row.col.f32.tf32.tf32.f32 "
                    "{%0,%1,%2,%3}, {%4,%5,%6,%7}, {%8,%9}, {%0,%1,%2,%3};"
                    : "+f"(acc[j][0]), "+f"(acc[j][1]), "+f"(acc[j][2]), "+f"(acc[j][3])
                    : "r"(a0), "r"(a1), "r"(a2), "r"(a3), "r"(b0), "r"(b1));
            }
        }
        __syncthreads();
    }

    int row0 = bm + warp * 16 + g;
    int row1 = row0 + 8;
    float sum0 = 0.0f, sum1 = 0.0f;
    #pragma unroll
    for (int j = 0; j < 8; j++) {
        int col = j * 8 + t * 2;
        float bb0 = 0.0f, bb1 = 0.0f;
        if (bias) { bb0 = bias[col]; bb1 = bias[col + 1]; }
        float2 r0 = *(const float2*)&X[(size_t)row0 * N + col];
        float2 r1 = *(const float2*)&X[(size_t)row1 * N + col];
        acc[j][0] += bb0 + r0.x; acc[j][1] += bb1 + r0.y;
        acc[j][2] += bb0 + r1.x; acc[j][3] += bb1 + r1.y;
        sum0 += acc[j][0] + acc[j][1];
        sum1 += acc[j][2] + acc[j][3];
    }
    sum0 += __shfl_xor_sync(0xffffffffu, sum0, 1);
    sum0 += __shfl_xor_sync(0xffffffffu, sum0, 2);
    sum1 += __shfl_xor_sync(0xffffffffu, sum1, 1);
    sum1 += __shfl_xor_sync(0xffffffffu, sum1, 2);
    float m0 = sum0 * (1.0f / 64.0f);
    float m1 = sum1 * (1.0f / 64.0f);
    float var0 = 0.0f, var1 = 0.0f;
    #pragma unroll
    for (int j = 0; j < 8; j++) {
        float d0 = acc[j][0] - m0, d1 = acc[j][1] - m0;
        float d2 = acc[j][2] - m1, d3 = acc[j][3] - m1;
        var0 += d0 * d0 + d1 * d1;
        var1 += d2 * d2 + d3 * d3;
    }
    var0 += __shfl_xor_sync(0xffffffffu, var0, 1);
    var0 += __shfl_xor_sync(0xffffffffu, var0, 2);
    var1 += __shfl_xor_sync(0xffffffffu, var1, 1);
    var1 += __shfl_xor_sync(0xffffffffu, var1, 2);
    float rs0 = rsqrtf(var0 * (1.0f / 64.0f) + 1e-5f);
    float rs1 = rsqrtf(var1 * (1.0f / 64.0f) + 1e-5f);
    #pragma unroll
    for (int j = 0; j < 8; j++) {
        int col = j * 8 + t * 2;
        float2 gg = *(const float2*)&gamma[col];
        float2 bb = *(const float2*)&beta[col];
        float2 w0, w1;
        w0.x = (acc[j][0] - m0) * rs0 * gg.x + bb.x;
        w0.y = (acc[j][1] - m0) * rs0 * gg.y + bb.y;
        w1.x = (acc[j][2] - m1) * rs1 * gg.x + bb.x;
        w1.y = (acc[j][3] - m1) * rs1 * gg.y + bb.y;
        *(float2*)&X[(size_t)row0 * N + col] = w0;
        *(float2*)&X[(size_t)row1 * N + col] = w1;
    }
}

// ---------------- GAT attention: warp per dst node, single-pass online softmax ----------------
__global__ __launch_bounds__(256) void gat_attn_kernel() {
    int warp = (blockIdx.x * blockDim.x + threadIdx.x) >> 5;
    int lane = threadIdx.x & 31;
    if (warp >= TOT) return;
    int node = warp;
    int beg = g_rowptr[node], end = g_rowptr[node + 1];
    const float2* q2 = (const float2*)g_q;     // stride 32 float2
    const float2* kv2 = (const float2*)g_kv;   // stride 64 float2: k then v
    float2 qv = q2[(size_t)node * 32 + lane];
    const float scale = 0.25f;  // 1/sqrt(16)
    float m = -INFINITY, denom = 0.0f, a0 = 0.0f, a1 = 0.0f;
    for (int e = beg; e < end; e++) {
        int s = g_csrc[e];
        float2 kv = kv2[(size_t)s * 64 + lane];
        float d = qv.x * kv.x + qv.y * kv.y;
        d += __shfl_xor_sync(0xffffffffu, d, 1);
        d += __shfl_xor_sync(0xffffffffu, d, 2);
        d += __shfl_xor_sync(0xffffffffu, d, 4);
        d *= scale;
        float mn = fmaxf(m, d);
        float f = __expf(m - mn);
        float w = __expf(d - mn);
        float2 vv = kv2[(size_t)s * 64 + 32 + lane];
        denom = denom * f + w;
        a0 = a0 * f + w * vv.x;
        a1 = a1 * f + w * vv.y;
        m = mn;
    }
    float invd = 1.0f / (denom + 1e-9f);
    float2 o; o.x = a0 * invd; o.y = a1 * invd;
    ((float2*)g_buf)[(size_t)node * 32 + lane] = o;
}

// ---------------- readout ----------------
__global__ void readout_kernel(const int* __restrict__ agent_nodes,
                               const float* __restrict__ Wr, const float* __restrict__ br)
{
    int i = blockIdx.x * blockDim.x + threadIdx.x;
    if (i >= NB * NA) return;
    int bi = i / NA, a = i % NA;
    int node = agent_nodes[bi];
    float s = br[a];
    #pragma unroll
    for (int h = 0; h < HDIM; h++) s += g_x[node * HDIM + h] * Wr[h * NA + a];
    g_gat[i] = s;
}

// ---------------- FC heads (fp32), 4-way ILP ----------------
__global__ __launch_bounds__(256) void fc_kernel(
    const float* __restrict__ A, const float* __restrict__ W,
    const float* __restrict__ bias, float* __restrict__ C,
    int in_dim, int out_dim, int act)
{
    __shared__ float srow[1536];
    int row = blockIdx.x;
    for (int i = threadIdx.x; i < in_dim; i += blockDim.x)
        srow[i] = A[row * in_dim + i];
    __syncthreads();
    int k4 = in_dim & ~3;
    for (int j = threadIdx.x; j < out_dim; j += blockDim.x) {
        float s0 = 0.f, s1 = 0.f, s2 = 0.f, s3 = 0.f;
        int k = 0;
        for (; k < k4; k += 4) {
            s0 += srow[k + 0] * W[(k + 0) * out_dim + j];
            s1 += srow[k + 1] * W[(k + 1) * out_dim + j];
            s2 += srow[k + 2] * W[(k + 2) * out_dim + j];
            s3 += srow[k + 3] * W[(k + 3) * out_dim + j];
        }
        for (; k < in_dim; k++) s0 += srow[k] * W[k * out_dim + j];
        float s = (bias ? bias[j] : 0.0f) + (s0 + s1) + (s2 + s3);
        if (act == 1) s = tanhf(s);
        C[row * out_dim + j] = s;
    }
}

__global__ __launch_bounds__(256) void fc_concat_kernel(
    const float* __restrict__ obs, const float* __restrict__ W,
    const float* __restrict__ bias)
{
    __shared__ float srow[1536];
    int row = blockIdx.x;
    for (int i = threadIdx.x; i < NA; i += blockDim.x) srow[i] = g_gat[row * NA + i];
    for (int i = threadIdx.x; i < OBSD; i += blockDim.x) srow[NA + i] = obs[row * OBSD + i];
    __syncthreads();
    const int in_dim = NA + OBSD;
    int k4 = in_dim & ~3;
    for (int j = threadIdx.x; j < HSD; j += blockDim.x) {
        float s0 = 0.f, s1 = 0.f, s2 = 0.f, s3 = 0.f;
        int k = 0;
        for (; k < k4; k += 4) {
            s0 += srow[k + 0] * W[(k + 0) * HSD + j];
            s1 += srow[k + 1] * W[(k + 1) * HSD + j];
            s2 += srow[k + 2] * W[(k + 2) * HSD + j];
            s3 += srow[k + 3] * W[(k + 3) * HSD + j];
        }
        for (; k < in_dim; k++) s0 += srow[k] * W[k * HSD + j];
        float s = bias[j] + (s0 + s1) + (s2 + s3);
        g_feat[row * HSD + j] = tanhf(s);
    }
}

__global__ void value_kernel(const float* __restrict__ Wvo, const float* __restrict__ bvo,
                             float* __restrict__ out)
{
    int bi = threadIdx.x;
    if (bi >= NB) return;
    float s = bvo[0];
    #pragma unroll
    for (int k = 0; k < VHD; k++) s += g_vh2[bi * VHD + k] * Wvo[k];
    out[NB * NOUTD + bi] = s;
}

// ---------------- launch ----------------
extern "C" void kernel_launch(void* const* d_in, const int* in_sizes, int n_in,
                              void* d_out, int out_size)
{
    const float* node_feats = (const float*)d_in[0];
    const float* obs        = (const float*)d_in[1];
    const int*   edge_src   = (const int*)d_in[2];
    const int*   edge_dst   = (const int*)d_in[3];
    const int*   agent_nodes= (const int*)d_in[4];
    const float* W_in = (const float*)d_in[5];
    const float* Wq   = (const float*)d_in[6];
    const float* Wk   = (const float*)d_in[7];
    const float* Wv   = (const float*)d_in[8];
    const float* Wo   = (const float*)d_in[9];
    const float* ln1g = (const float*)d_in[10];
    const float* ln1b = (const float*)d_in[11];
    const float* W1   = (const float*)d_in[12];
    const float* b1   = (const float*)d_in[13];
    const float* W2   = (const float*)d_in[14];
    const float* b2   = (const float*)d_in[15];
    const float* ln2g = (const float*)d_in[16];
    const float* ln2b = (const float*)d_in[17];
    const float* Wr   = (const float*)d_in[18];
    const float* br   = (const float*)d_in[19];
    const float* Wp1  = (const float*)d_in[20];
    const float* bp1  = (const float*)d_in[21];
    const float* Wp2  = (const float*)d_in[22];
    const float* bp2  = (const float*)d_in[23];
    const float* Wlog = (const float*)d_in[24];
    const float* blog = (const float*)d_in[25];
    const float* Wv1  = (const float*)d_in[26];
    const float* bv1  = (const float*)d_in[27];
    const float* Wv2  = (const float*)d_in[28];
    const float* bv2  = (const float*)d_in[29];
    const float* Wvo  = (const float*)d_in[30];
    const float* bvo  = (const float*)d_in[31];
    float* out = (float*)d_out;

    float *x, *q, *kv, *buf, *hid, *wqkv, *feat, *feat2, *vh, *vh2;
    cudaGetSymbolAddress((void**)&x,    g_x);
    cudaGetSymbolAddress((void**)&q,    g_q);
    cudaGetSymbolAddress((void**)&kv,   g_kv);
    cudaGetSymbolAddress((void**)&buf,  g_buf);
    cudaGetSymbolAddress((void**)&hid,  g_hid);
    cudaGetSymbolAddress((void**)&wqkv, g_wqkv);
    cudaGetSymbolAddress((void**)&feat, g_feat);
    cudaGetSymbolAddress((void**)&feat2,g_feat2);
    cudaGetSymbolAddress((void**)&vh,   g_vh);
    cudaGetSymbolAddress((void**)&vh2,  g_vh2);

    const int MB = TOT / 128;  // 1000 row blocks

    // CSR build + weight packing
    zero_counts_kernel<<<(TOT + 255) / 256, 256>>>();
    count_edges_kernel<<<(NEDGE + 255) / 256, 256>>>(edge_dst);
    scan_kernel<<<1, 1024>>>();
    scatter_edges_kernel<<<(NEDGE + 255) / 256, 256>>>(edge_src, edge_dst);
    pack_qkv_kernel<<<(NLAYER * HDIM * HDIM + 255) / 256, 256>>>(Wq, Wk, Wv);

    // input projection: x = node_feats @ W_in   [TOT,32]@[32,64]
    gemm_tf32_kernel<<<dim3(1, MB), 256>>>(node_feats, W_in, nullptr, x, 64, 32, 0);

    for (int l = 0; l < NLAYER; l++) {
        // fused QKV projection -> q (stream) + packed kv (gather set)
        gemm_qkv_kernel<<<dim3(3, MB), 256>>>(x, wqkv + l * HDIM * 192, q, kv);
        gat_attn_kernel<<<TOT / 8, 256>>>();
        // x = LN(x + buf @ Wo_l)
        gemm_tf32_ln_kernel<<<dim3(1, MB), 256>>>(buf, Wo + l * HDIM * HDIM, nullptr,
                                                  x, ln1g + l * HDIM, ln1b + l * HDIM, 64);
        // hid = relu(x @ W1_l + b1_l)
        gemm_tf32_kernel<<<dim3(2, MB), 256>>>(x, W1 + l * HDIM * 2 * HDIM, b1 + l * 2 * HDIM,
                                               hid, 2 * HDIM, HDIM, 1);
        // x = LN(x + hid @ W2_l + b2_l)
        gemm_tf32_ln_kernel<<<dim3(1, MB), 256>>>(hid, W2 + l * 2 * HDIM * HDIM, b2 + l * HDIM,
                                                  x, ln2g + l * HDIM, ln2b + l * HDIM, 128);
    }

    // heads (fp32, small)
    readout_kernel<<<(NB * NA + 255) / 256, 256>>>(agent_nodes, Wr, br);
    fc_concat_kernel<<<NB, 256>>>(obs, Wp1, bp1);
    fc_kernel<<<NB, 256>>>(feat, Wp2, bp2, feat2, HSD, HSD, 1);
    fc_kernel<<<NB, 256>>>(feat2, Wlog, blog, out, HSD, NOUTD, 0);
    fc_kernel<<<NB, 256>>>(obs, Wv1, bv1, vh, OBSD, VHD, 1);
    fc_kernel<<<NB, 256>>>(vh, Wv2, bv2, vh2, VHD, VHD, 1);
    value_kernel<<<1, 128>>>(Wvo, bvo, out);
}